// round 2
// baseline (speedup 1.0000x reference)
#include <cuda_runtime.h>
#include <cstdint>

#define G     34
#define GP    36
#define NPIX  1156
#define NPAD  1296
#define TPB   320
#define ACT   289
#define HID   64
#define BATCH 1024

// packed f32x2 FMA (Blackwell FFMA2; only reachable via PTX)
__device__ __forceinline__ float2 ffma2(float2 a, float2 b, float2 c) {
    float2 d;
    asm("{\n\t"
        ".reg .b64 ra, rb, rc;\n\t"
        "mov.b64 ra, {%2, %3};\n\t"
        "mov.b64 rb, {%4, %5};\n\t"
        "mov.b64 rc, {%6, %7};\n\t"
        "fma.rn.f32x2 rc, ra, rb, rc;\n\t"
        "mov.b64 {%0, %1}, rc;\n\t"
        "}"
        : "=f"(d.x), "=f"(d.y)
        : "f"(a.x), "f"(a.y), "f"(b.x), "f"(b.y), "f"(c.x), "f"(c.y));
    return d;
}

__device__ __forceinline__ float max9(const float* p) {
    float m = fmaxf(fmaxf(p[-GP-1], p[-GP]), fmaxf(p[-GP+1], p[-1]));
    m = fmaxf(m, fmaxf(fmaxf(p[0], p[1]),
              fmaxf(p[GP-1], fmaxf(p[GP], p[GP+1]))));
    return m;
}

__global__ __launch_bounds__(TPB, 2)
void ca_kernel(
    const float* __restrict__ cell_g, const float* __restrict__ food_g,
    const float* __restrict__ fc1w,   const float* __restrict__ fc1b,
    const float* __restrict__ fc2w,   const float* __restrict__ fc2b,
    const float* __restrict__ skg,    const int* __restrict__ steps_p,
    float* __restrict__ out)
{
    __shared__ float  cs[4][NPAD];       // cell channels, 36x36 zero-halo
    __shared__ float  xb[NPAD];          // scratch: food, then raw x0
    __shared__ float  scent_s[NPIX];
    __shared__ float4 w1q[HID][6];       // fc1 weights, duplicated pairs
    __shared__ float4 w2q[HID][2];       // fc2^T weights, duplicated pairs
    __shared__ float2 b1p[HID];
    __shared__ float  sk[361];
    __shared__ float  b2s[4];
    __shared__ unsigned int hist[256];
    __shared__ int    s_cl;
    __shared__ unsigned int s_kk, s_pref;
    __shared__ float  s_sum;
    __shared__ int    s_lc;

    const int b    = blockIdx.x;
    const int tid  = threadIdx.x;
    const int lane = tid & 31;
    const bool act = tid < ACT;
    const float* cellb = cell_g + (size_t)b * 4 * NPIX;
    const float* foodb = food_g + (size_t)b * NPIX;

    for (int idx = tid; idx < 4 * NPAD; idx += TPB) ((float*)cs)[idx] = 0.f;
    for (int idx = tid; idx < NPAD; idx += TPB) xb[idx] = 0.f;
    __syncthreads();

    for (int idx = tid; idx < 4 * NPIX; idx += TPB) {
        int c = idx / NPIX, p = idx - c * NPIX;
        int i = p / G, j = p - i * G;
        cs[c][(i + 1) * GP + (j + 1)] = cellb[idx];
    }
    for (int idx = tid; idx < NPIX; idx += TPB) xb[idx] = foodb[idx];   // food (unpadded)
    for (int idx = tid; idx < 768; idx += TPB) {
        float w = fc1w[idx];
        ((float2*)w1q)[idx] = make_float2(w, w);                        // [o][c] dup
    }
    for (int idx = tid; idx < 256; idx += TPB) {
        int o = idx >> 6, j = idx & 63;
        float w = fc2w[idx];
        ((float2*)w2q)[j * 4 + o] = make_float2(w, w);                  // transposed dup
    }
    for (int idx = tid; idx < HID; idx += TPB) {
        float v = fc1b[idx];
        b1p[idx] = make_float2(v, v);
    }
    for (int idx = tid; idx < 361; idx += TPB) sk[idx] = skg[idx];
    if (tid < 4) b2s[tid] = fc2b[tid];
    if (tid == 0) { s_cl = 0; s_sum = 0.f; s_lc = 0; }

    int steps = steps_p[0];
    if (steps < 0 || steps > 1000000) {        // defensive: steps stored as f32
        float f = __int_as_float(steps);
        steps = (int)f;
    }

    int pbase[4] = {0, 0, 0, 0};
    __syncthreads();

    // ---- scent: 19x19 cross-correlation, pad 9 (constant over steps) ----
    if (act) {
        #pragma unroll
        for (int k = 0; k < 4; k++) {
            int p = tid + ACT * k;
            int i = p / G, j = p - i * G;
            pbase[k] = (i + 1) * GP + (j + 1);
            float s = 0.f;
            for (int a = 0; a < 19; a++) {
                int ii = i + a - 9;
                if ((unsigned)ii < (unsigned)G) {
                    const float* kr = &sk[a * 19];
                    const float* fr = &xb[ii * G];
                    for (int bb = 0; bb < 19; bb++) {
                        int jj = j + bb - 9;
                        if ((unsigned)jj < (unsigned)G) s = fmaf(kr[bb], fr[jj], s);
                    }
                }
            }
            scent_s[p] = s;
        }
    }
    __syncthreads();
    for (int idx = tid; idx < NPAD; idx += TPB) xb[idx] = 0.f;  // xb -> x0 scratch (zero halo)

    // ======================= main step loop =======================
    for (int st = 0; st < steps; ++st) {
        __syncthreads();                                  // S0

        // Phase A: chan3 = scent; cl = count(cell0 > 0.8) pre-update
        int cnt = 0;
        if (act) {
            #pragma unroll
            for (int k = 0; k < 4; k++) {
                cs[3][pbase[k]] = scent_s[tid + ACT * k];
                cnt += (cs[0][pbase[k]] > 0.8f) ? 1 : 0;
            }
        }
        #pragma unroll
        for (int o = 16; o; o >>= 1) cnt += __shfl_xor_sync(0xffffffffu, cnt, o);
        if (lane == 0 && cnt) atomicAdd(&s_cl, cnt);
        __syncthreads();                                  // S1

        // Phase B: perception + MLP; x = cell + upd (raw); write x0 to xb
        float2 yp[2][12];
        float  X[4][4];
        int    premask = 0;
        if (act) {
            #pragma unroll
            for (int k = 0; k < 4; k++) {
                const int bi = pbase[k];
                float mx = 0.f;
                #pragma unroll
                for (int c = 0; c < 4; c++) {
                    const float* p = &cs[c][bi];
                    float n00 = p[-GP-1], n01 = p[-GP], n02 = p[-GP+1];
                    float n10 = p[-1],    n11 = p[0],   n12 = p[1];
                    float n20 = p[GP-1],  n21 = p[GP],  n22 = p[GP+1];
                    float sx = ((n02 - n00) + 2.f * (n12 - n10) + (n22 - n20)) * 0.125f;
                    float sy = ((n20 - n00) + 2.f * (n21 - n01) + (n22 - n02)) * 0.125f;
                    if (c == 0)
                        mx = fmaxf(fmaxf(fmaxf(n00, n01), fmaxf(n02, n10)),
                                   fmaxf(fmaxf(n11, n12),
                                         fmaxf(n20, fmaxf(n21, n22))));
                    if (k & 1) {
                        yp[k >> 1][c].y = n11; yp[k >> 1][4 + c].y = sx; yp[k >> 1][8 + c].y = sy;
                    } else {
                        yp[k >> 1][c].x = n11; yp[k >> 1][4 + c].x = sx; yp[k >> 1][8 + c].x = sy;
                    }
                }
                if (mx > 0.1f) premask |= (1 << k);
            }

            float2 A0[4], A1[4];
            #pragma unroll
            for (int c = 0; c < 4; c++) {
                float bv = b2s[c];
                A0[c] = make_float2(bv, bv);
                A1[c] = make_float2(bv, bv);
            }
            #pragma unroll 4
            for (int j = 0; j < HID; j++) {
                const float4* wr = w1q[j];
                float2 h0 = b1p[j], h1 = h0;
                #pragma unroll
                for (int cc = 0; cc < 6; cc++) {
                    float4 w = wr[cc];
                    float2 wl = make_float2(w.x, w.y);
                    float2 wh = make_float2(w.z, w.w);
                    h0 = ffma2(wl, yp[0][2 * cc],     h0);
                    h0 = ffma2(wh, yp[0][2 * cc + 1], h0);
                    h1 = ffma2(wl, yp[1][2 * cc],     h1);
                    h1 = ffma2(wh, yp[1][2 * cc + 1], h1);
                }
                h0.x = fmaxf(h0.x, 0.f); h0.y = fmaxf(h0.y, 0.f);
                h1.x = fmaxf(h1.x, 0.f); h1.y = fmaxf(h1.y, 0.f);
                float4 v0 = w2q[j][0], v1 = w2q[j][1];
                float2 u0 = make_float2(v0.x, v0.y), u1 = make_float2(v0.z, v0.w);
                float2 u2 = make_float2(v1.x, v1.y), u3 = make_float2(v1.z, v1.w);
                A0[0] = ffma2(u0, h0, A0[0]); A0[1] = ffma2(u1, h0, A0[1]);
                A0[2] = ffma2(u2, h0, A0[2]); A0[3] = ffma2(u3, h0, A0[3]);
                A1[0] = ffma2(u0, h1, A1[0]); A1[1] = ffma2(u1, h1, A1[1]);
                A1[2] = ffma2(u2, h1, A1[2]); A1[3] = ffma2(u3, h1, A1[3]);
            }
            #pragma unroll
            for (int c = 0; c < 4; c++) {
                X[c][0] = yp[0][c].x + A0[c].x;
                X[c][1] = yp[0][c].y + A0[c].y;
                X[c][2] = yp[1][c].x + A1[c].x;
                X[c][3] = yp[1][c].y + A1[c].y;
            }
            #pragma unroll
            for (int k = 0; k < 4; k++) xb[pbase[k]] = X[0][k];  // raw x0
        }
        __syncthreads();                                  // S2

        // Phase C: post mask (on raw x0), mask + clip, write channels
        float v0f[4] = {0.f, 0.f, 0.f, 0.f};
        if (act) {
            #pragma unroll
            for (int k = 0; k < 4; k++) {
                const int bi = pbase[k];
                bool keep = ((premask >> k) & 1) && (max9(&xb[bi]) > 0.1f);
                float v0 = keep ? X[0][k] : 0.f;
                float v1 = keep ? X[1][k] : 0.f;
                float v2 = keep ? X[2][k] : 0.f;
                float v3 = keep ? X[3][k] : 0.f;
                v0 = fminf(fmaxf(v0, 0.f), 1.f);
                v1 = fminf(fmaxf(v1, -10.f), 10.f);
                v2 = fminf(fmaxf(v2, -10.f), 10.f);
                v3 = fminf(fmaxf(v3, -10.f), 10.f);
                cs[0][bi] = v0; cs[1][bi] = v1; cs[2][bi] = v2; cs[3][bi] = v3;
                v0f[k] = v0;
            }
        }
        if (tid == 0) {
            int k = s_cl; if (k > NPIX - 1) k = NPIX - 1;
            s_kk = (unsigned)k;
            s_pref = 0u;
        }

        // Phase D: exact k-th smallest via 4-pass radix-256 select on f32 bits
        #pragma unroll
        for (int ps = 3; ps >= 0; --ps) {
            const int sh = ps * 8;
            __syncthreads();
            if (tid < 256) hist[tid] = 0u;
            __syncthreads();
            unsigned pref = s_pref;
            if (act) {
                #pragma unroll
                for (int k = 0; k < 4; k++) {
                    unsigned bits = __float_as_uint(v0f[k]);
                    bool m = (ps == 3) || ((bits >> (sh + 8)) == (pref >> (sh + 8)));
                    if (m) atomicAdd(&hist[(bits >> sh) & 255u], 1u);
                }
            }
            __syncthreads();
            if (tid < 32) {
                unsigned c[8];
                #pragma unroll
                for (int i = 0; i < 8; i++) c[i] = hist[lane * 8 + i];
                unsigned tot = c[0]+c[1]+c[2]+c[3]+c[4]+c[5]+c[6]+c[7];
                unsigned incl = tot;
                #pragma unroll
                for (int o = 1; o < 32; o <<= 1) {
                    unsigned v = __shfl_up_sync(0xffffffffu, incl, o);
                    if (lane >= o) incl += v;
                }
                unsigned kk = s_kk;
                unsigned ball = __ballot_sync(0xffffffffu, incl > kk);
                int src = __ffs(ball) - 1;
                if (lane == src) {
                    unsigned cum = incl - tot;
                    #pragma unroll
                    for (int i = 0; i < 8; i++) {
                        if (cum + c[i] > kk) {
                            s_pref = pref | ((unsigned)(lane * 8 + i) << sh);
                            s_kk   = kk - cum;
                            break;
                        }
                        cum += c[i];
                    }
                }
            }
        }
        __syncthreads();
        float kth = __uint_as_float(s_pref);
        if (act) {
            #pragma unroll
            for (int k = 0; k < 4; k++)
                if (!(v0f[k] > kth)) { cs[0][pbase[k]] = 0.f; v0f[k] = 0.f; }
        }
        if (tid == 0) s_cl = 0;
    }
    __syncthreads();

    // ---- outputs: [cell | food | total_pixel_val | living_count] ----
    float* out_cell = out;
    float* out_food = out + (size_t)BATCH * 4 * NPIX;
    float* out_tot  = out + (size_t)BATCH * 5 * NPIX;
    float* out_lc   = out_tot + BATCH;

    for (int idx = tid; idx < 4 * NPIX; idx += TPB) {
        int c = idx / NPIX, p = idx - c * NPIX;
        int i = p / G, j = p - i * G;
        out_cell[(size_t)b * 4 * NPIX + idx] = cs[c][(i + 1) * GP + (j + 1)];
    }
    for (int idx = tid; idx < NPIX; idx += TPB)
        out_food[(size_t)b * NPIX + idx] = foodb[idx];

    float psum = 0.f; int plc = 0;
    if (act) {
        #pragma unroll
        for (int k = 0; k < 4; k++) {
            float v = cs[0][pbase[k]];
            psum += v;
            plc  += (v > 0.1f) ? 1 : 0;
        }
    }
    #pragma unroll
    for (int o = 16; o; o >>= 1) {
        psum += __shfl_xor_sync(0xffffffffu, psum, o);
        plc  += __shfl_xor_sync(0xffffffffu, plc, o);
    }
    if (lane == 0) {
        atomicAdd(&s_sum, psum);
        atomicAdd(&s_lc, plc);
    }
    __syncthreads();
    if (tid == 0) {
        out_tot[b] = s_sum;
        out_lc[b]  = (float)s_lc;
    }
}

extern "C" void kernel_launch(void* const* d_in, const int* in_sizes, int n_in,
                              void* d_out, int out_size) {
    const float* cell = (const float*)d_in[0];
    const float* food = (const float*)d_in[1];
    const float* fc1w = (const float*)d_in[2];
    const float* fc1b = (const float*)d_in[3];
    const float* fc2w = (const float*)d_in[4];
    const float* fc2b = (const float*)d_in[5];
    const float* skg  = (const float*)d_in[6];
    const int*   stp  = (const int*)d_in[7];
    float* out = (float*)d_out;
    ca_kernel<<<BATCH, TPB>>>(cell, food, fc1w, fc1b, fc2w, fc2b, skg, stp, out);
}